// round 2
// baseline (speedup 1.0000x reference)
#include <cuda_runtime.h>
#include <math.h>

// ---------------------------------------------------------------------------
// SelfTransFormer: Q/K/V conv1x1 projections + BatchNorm(training) + LeakyReLU,
// then per-head "KV attention": H = softmax_j(K^T V / sqrt(dh)), out = sum_j H Q.
// B=8, CIN=512, COUT=1024, P=2048, H=8, dh=128.
// ---------------------------------------------------------------------------

#define BB   8
#define CIN  512
#define COUT 1024
#define PP   2048
#define NH   8
#define DH   128
#define EPSF 1e-5f

// scratch: Y[proj][b][cout][p], proj 0=Q,1=K,2=V  (192 MB)
static __device__ float g_Y[(size_t)3 * BB * COUT * PP];
// per (proj, channel): {scale, shift}
static __device__ float2 g_ss[3 * COUT];

// ---------------------------------------------------------------------------
// 1) Projection GEMM: Y[proj][b] = W_proj [1024x512] * X_b [512x2048]
//    128x128 tile, K-tile 8, 256 threads, 8x8 microtile, reg-prefetch dbuf.
// ---------------------------------------------------------------------------
__global__ void __launch_bounds__(256)
proj_gemm_kernel(const float* __restrict__ x,
                 const float* __restrict__ Wq,
                 const float* __restrict__ Wk,
                 const float* __restrict__ Wv)
{
    const int proj = blockIdx.z >> 3;       // 0..2
    const int b    = blockIdx.z & 7;        // 0..7
    const float* __restrict__ W = (proj == 0) ? Wq : ((proj == 1) ? Wk : Wv);
    const float* __restrict__ X = x + (size_t)b * CIN * PP;
    float* __restrict__ C = g_Y + ((size_t)(proj * BB + b) * COUT) * PP;

    const int row0 = blockIdx.y * 128;
    const int col0 = blockIdx.x * 128;

    __shared__ float As[2][8][128];
    __shared__ float Bs[2][8][128];

    const int t  = threadIdx.x;
    const int tx = t & 15;
    const int ty = t >> 4;
    const int tx8 = tx * 8, ty8 = ty * 8;

    // global load assignments (1 float4 each per tile)
    const int ar = t >> 1;           // 0..127 (W row within tile)
    const int ak = (t & 1) * 4;      // 0 or 4 (k offset)
    const int bk = t >> 5;           // 0..7   (k row)
    const int bc = (t & 31) * 4;     // 0..124 (col offset)

    float4 pa = *(const float4*)&W[(size_t)(row0 + ar) * CIN + ak];
    float4 pb = *(const float4*)&X[(size_t)bk * PP + col0 + bc];

    As[0][ak + 0][ar] = pa.x;
    As[0][ak + 1][ar] = pa.y;
    As[0][ak + 2][ar] = pa.z;
    As[0][ak + 3][ar] = pa.w;
    *(float4*)&Bs[0][bk][bc] = pb;
    __syncthreads();

    float acc[8][8];
#pragma unroll
    for (int r = 0; r < 8; r++)
#pragma unroll
        for (int q = 0; q < 8; q++) acc[r][q] = 0.f;

    const int KT = CIN / 8;  // 64
    for (int kt = 0; kt < KT; kt++) {
        const int cur = kt & 1;
        if (kt < KT - 1) {
            const int k0 = (kt + 1) * 8;
            pa = *(const float4*)&W[(size_t)(row0 + ar) * CIN + k0 + ak];
            pb = *(const float4*)&X[(size_t)(k0 + bk) * PP + col0 + bc];
        }
#pragma unroll
        for (int kk = 0; kk < 8; kk++) {
            float4 a0 = *(float4*)&As[cur][kk][ty8];
            float4 a1 = *(float4*)&As[cur][kk][ty8 + 4];
            float4 b0 = *(float4*)&Bs[cur][kk][tx8];
            float4 b1 = *(float4*)&Bs[cur][kk][tx8 + 4];
            float av[8] = {a0.x, a0.y, a0.z, a0.w, a1.x, a1.y, a1.z, a1.w};
            float bv[8] = {b0.x, b0.y, b0.z, b0.w, b1.x, b1.y, b1.z, b1.w};
#pragma unroll
            for (int r = 0; r < 8; r++)
#pragma unroll
                for (int q = 0; q < 8; q++)
                    acc[r][q] = fmaf(av[r], bv[q], acc[r][q]);
        }
        if (kt < KT - 1) {
            const int nxt = cur ^ 1;
            As[nxt][ak + 0][ar] = pa.x;
            As[nxt][ak + 1][ar] = pa.y;
            As[nxt][ak + 2][ar] = pa.z;
            As[nxt][ak + 3][ar] = pa.w;
            *(float4*)&Bs[nxt][bk][bc] = pb;
            __syncthreads();
        }
    }

#pragma unroll
    for (int r = 0; r < 8; r++) {
        float* crow = C + (size_t)(row0 + ty8 + r) * PP + col0 + tx8;
        *(float4*)(crow)     = make_float4(acc[r][0], acc[r][1], acc[r][2], acc[r][3]);
        *(float4*)(crow + 4) = make_float4(acc[r][4], acc[r][5], acc[r][6], acc[r][7]);
    }
}

// ---------------------------------------------------------------------------
// 2) BN stats per (proj, channel): mean/var over (B,P) = 16384 elems (biased).
// ---------------------------------------------------------------------------
__global__ void __launch_bounds__(256)
stats_kernel(const float* __restrict__ gq, const float* __restrict__ bq,
             const float* __restrict__ gk, const float* __restrict__ bk,
             const float* __restrict__ gv, const float* __restrict__ bv)
{
    const int o    = blockIdx.x & (COUT - 1);
    const int proj = blockIdx.x >> 10;
    const int tid  = threadIdx.x;

    float s = 0.f, ss = 0.f;
    for (int b = 0; b < BB; b++) {
        const float4* row = (const float4*)(g_Y + (((size_t)(proj * BB + b) * COUT + o) * PP));
#pragma unroll
        for (int i = tid; i < PP / 4; i += 256) {
            float4 v = row[i];
            s  += v.x + v.y + v.z + v.w;
            ss += v.x * v.x + v.y * v.y + v.z * v.z + v.w * v.w;
        }
    }
#pragma unroll
    for (int off = 16; off; off >>= 1) {
        s  += __shfl_down_sync(0xffffffffu, s, off);
        ss += __shfl_down_sync(0xffffffffu, ss, off);
    }
    __shared__ float ws[8], wss[8];
    if ((tid & 31) == 0) { ws[tid >> 5] = s; wss[tid >> 5] = ss; }
    __syncthreads();
    if (tid == 0) {
        float S = 0.f, SS = 0.f;
#pragma unroll
        for (int i = 0; i < 8; i++) { S += ws[i]; SS += wss[i]; }
        const float invN = 1.0f / (float)(BB * PP);
        float mean = S * invN;
        float var  = SS * invN - mean * mean;
        float g    = (proj == 0) ? gq[o] : ((proj == 1) ? gk[o] : gv[o]);
        float be   = (proj == 0) ? bq[o] : ((proj == 1) ? bk[o] : bv[o]);
        float scale = g * rsqrtf(var + EPSF);
        g_ss[blockIdx.x] = make_float2(scale, be - mean * scale);
    }
}

// ---------------------------------------------------------------------------
// 3) Normalize + LeakyReLU(0.1) in place.
// ---------------------------------------------------------------------------
__global__ void __launch_bounds__(256)
norm_kernel()
{
    const size_t i4 = (size_t)blockIdx.x * 256 + threadIdx.x;   // float4 index
    const size_t e  = i4 * 4;
    const int o    = (int)((e >> 11) & (COUT - 1));
    const int proj = (int)(e >> 24);   // / (8*1024*2048)
    const float2 ss = g_ss[proj * COUT + o];
    float4* Y4 = (float4*)g_Y;
    float4 v = Y4[i4];
    float a = fmaf(v.x, ss.x, ss.y);
    float bq_ = fmaf(v.y, ss.x, ss.y);
    float c = fmaf(v.z, ss.x, ss.y);
    float d = fmaf(v.w, ss.x, ss.y);
    v.x = (a   >= 0.f) ? a   : 0.1f * a;
    v.y = (bq_ >= 0.f) ? bq_ : 0.1f * bq_;
    v.z = (c   >= 0.f) ? c   : 0.1f * c;
    v.w = (d   >= 0.f) ? d   : 0.1f * d;
    Y4[i4] = v;
}

// ---------------------------------------------------------------------------
// 4) Flash attention. Per block: one (b, h, 64-row i-tile).
//    "queries" = K columns, "keys" = V columns, "values" = Q columns.
//    S[i,j] = sum_c K[c,i] V[c,j] / sqrt(dh); softmax over j;
//    out[c,i] = sum_j P[i,j] Q[c,j].
// ---------------------------------------------------------------------------
#define TI 64
#define TJ 64
#define ATTN_SMEM_FLOATS (8192 + 8192 + 64*132 + 64*68 + 192)
#define ATTN_SMEM_BYTES  (ATTN_SMEM_FLOATS * 4)

__global__ void __launch_bounds__(256)
attn_kernel(float* __restrict__ out)
{
    extern __shared__ float sm[];
    float* Kf  = sm;                       // [128][64]
    float* Vf  = sm + 8192;                // [128][64]
    float* QfT = sm + 16384;               // [64][132]  (transposed: [jj][c])
    float* ST  = sm + 16384 + 64 * 132;    // [64][68]   (transposed: [jj][ii])
    float* m_s = ST + 64 * 68;
    float* l_s = m_s + 64;
    float* f_s = l_s + 64;

    const float* __restrict__ Qn = g_Y;
    const float* __restrict__ Kn = g_Y + (size_t)BB * COUT * PP;
    const float* __restrict__ Vn = g_Y + (size_t)2 * BB * COUT * PP;

    const int tid = threadIdx.x;
    const int tx = tid & 15, ty = tid >> 4;
    const int i0 = blockIdx.x * TI;
    const int h  = blockIdx.y;
    const int b  = blockIdx.z;
    const size_t headBase = ((size_t)b * COUT + h * DH) * PP;
    const float rscale = 0.08838834764831845f;  // 1/sqrt(128)
    const float NEG_BIG = -1e30f;

    // Load K tile (persistent): Kf[c][ii]
#pragma unroll
    for (int it = 0; it < 8; it++) {
        int lin = tid + it * 256;            // 0..2047
        int c = lin >> 4, c4 = (lin & 15) << 2;
        float4 v = *(const float4*)&Kn[headBase + (size_t)c * PP + i0 + c4];
        *(float4*)&Kf[c * 64 + c4] = v;
    }
    if (tid < 64) { m_s[tid] = NEG_BIG; l_s[tid] = 0.f; }

    float acc[8][4];
#pragma unroll
    for (int r = 0; r < 8; r++)
#pragma unroll
        for (int q = 0; q < 4; q++) acc[r][q] = 0.f;

    for (int j0 = 0; j0 < PP; j0 += TJ) {
        __syncthreads();   // protect Vf/QfT/ST from previous iteration readers
        // Load V tile ([c][jj]) and Q tile (transposed [jj][c])
#pragma unroll
        for (int it = 0; it < 8; it++) {
            int lin = tid + it * 256;
            int c = lin >> 4, c4 = (lin & 15) << 2;
            float4 v = *(const float4*)&Vn[headBase + (size_t)c * PP + j0 + c4];
            *(float4*)&Vf[c * 64 + c4] = v;
            float4 qv = *(const float4*)&Qn[headBase + (size_t)c * PP + j0 + c4];
            QfT[(c4 + 0) * 132 + c] = qv.x;
            QfT[(c4 + 1) * 132 + c] = qv.y;
            QfT[(c4 + 2) * 132 + c] = qv.z;
            QfT[(c4 + 3) * 132 + c] = qv.w;
        }
        __syncthreads();

        // S gemm: thread -> ii = ty*4+r, jj = tx*4+q
        float s[4][4];
#pragma unroll
        for (int r = 0; r < 4; r++)
#pragma unroll
            for (int q = 0; q < 4; q++) s[r][q] = 0.f;
#pragma unroll 8
        for (int c = 0; c < DH; c++) {
            float4 a  = *(float4*)&Kf[c * 64 + ty * 4];
            float4 bb = *(float4*)&Vf[c * 64 + tx * 4];
            float av[4] = {a.x, a.y, a.z, a.w};
            float bv[4] = {bb.x, bb.y, bb.z, bb.w};
#pragma unroll
            for (int r = 0; r < 4; r++)
#pragma unroll
                for (int q = 0; q < 4; q++)
                    s[r][q] = fmaf(av[r], bv[q], s[r][q]);
        }
        // write transposed + scaled: ST[jj][ii]
#pragma unroll
        for (int q = 0; q < 4; q++) {
            float4 w = make_float4(s[0][q] * rscale, s[1][q] * rscale,
                                   s[2][q] * rscale, s[3][q] * rscale);
            *(float4*)&ST[(tx * 4 + q) * 68 + ty * 4] = w;
        }
        __syncthreads();

        // Online softmax: 4 threads per row ii, interleaved jj scan
        {
            const int ii = tid >> 2, sg = tid & 3;
            float mx = NEG_BIG;
#pragma unroll
            for (int k = 0; k < 16; k++)
                mx = fmaxf(mx, ST[(sg + 4 * k) * 68 + ii]);
            mx = fmaxf(mx, __shfl_xor_sync(0xffffffffu, mx, 1));
            mx = fmaxf(mx, __shfl_xor_sync(0xffffffffu, mx, 2));
            const float m_new = fmaxf(m_s[ii], mx);
            float se = 0.f;
#pragma unroll
            for (int k = 0; k < 16; k++) {
                const int jj = sg + 4 * k;
                float p = __expf(ST[jj * 68 + ii] - m_new);
                ST[jj * 68 + ii] = p;
                se += p;
            }
            se += __shfl_xor_sync(0xffffffffu, se, 1);
            se += __shfl_xor_sync(0xffffffffu, se, 2);
            if (sg == 0) {
                float f = __expf(m_s[ii] - m_new);
                l_s[ii] = l_s[ii] * f + se;
                m_s[ii] = m_new;
                f_s[ii] = f;
            }
        }
        __syncthreads();

        // Rescale accumulators; O gemm: thread -> ii = tx*4+q, c = ty*8+r
#pragma unroll
        for (int q = 0; q < 4; q++) {
            float f = f_s[tx * 4 + q];
#pragma unroll
            for (int r = 0; r < 8; r++) acc[r][q] *= f;
        }
#pragma unroll 4
        for (int jj = 0; jj < TJ; jj++) {
            float4 p  = *(float4*)&ST[jj * 68 + tx * 4];
            float4 qa = *(float4*)&QfT[jj * 132 + ty * 8];
            float4 qb = *(float4*)&QfT[jj * 132 + ty * 8 + 4];
            float qq[8] = {qa.x, qa.y, qa.z, qa.w, qb.x, qb.y, qb.z, qb.w};
            float pp[4] = {p.x, p.y, p.z, p.w};
#pragma unroll
            for (int r = 0; r < 8; r++)
#pragma unroll
                for (int q = 0; q < 4; q++)
                    acc[r][q] = fmaf(qq[r], pp[q], acc[r][q]);
        }
    }

    // Epilogue: out[b][h*128 + c][i0 + ii] = acc / l
    float inv[4];
#pragma unroll
    for (int q = 0; q < 4; q++) inv[q] = 1.0f / l_s[tx * 4 + q];
#pragma unroll
    for (int r = 0; r < 8; r++) {
        const int c = ty * 8 + r;
        float4 w = make_float4(acc[r][0] * inv[0], acc[r][1] * inv[1],
                               acc[r][2] * inv[2], acc[r][3] * inv[3]);
        *(float4*)&out[headBase + (size_t)c * PP + i0 + tx * 4] = w;
    }
}

// ---------------------------------------------------------------------------
extern "C" void kernel_launch(void* const* d_in, const int* in_sizes, int n_in,
                              void* d_out, int out_size)
{
    const float* x  = (const float*)d_in[0];
    const float* Wq = (const float*)d_in[1];
    const float* gq = (const float*)d_in[2];
    const float* bq = (const float*)d_in[3];
    const float* Wk = (const float*)d_in[4];
    const float* gk = (const float*)d_in[5];
    const float* bk = (const float*)d_in[6];
    const float* Wv = (const float*)d_in[7];
    const float* gv = (const float*)d_in[8];
    const float* bv = (const float*)d_in[9];
    float* out = (float*)d_out;

    (void)in_sizes; (void)n_in; (void)out_size;

    proj_gemm_kernel<<<dim3(PP / 128, COUT / 128, 24), 256>>>(x, Wq, Wk, Wv);
    stats_kernel<<<3 * COUT, 256>>>(gq, bq, gk, bk, gv, bv);
    norm_kernel<<<(3u * BB * COUT * PP / 4) / 256, 256>>>();

    cudaFuncSetAttribute(attn_kernel,
                         cudaFuncAttributeMaxDynamicSharedMemorySize,
                         ATTN_SMEM_BYTES);
    attn_kernel<<<dim3(PP / TI, NH, BB), 256, ATTN_SMEM_BYTES>>>(out);
}

// round 3
// speedup vs baseline: 2.6014x; 2.6014x over previous
#include <cuda_runtime.h>
#include <math.h>
#include <stdint.h>

// ---------------------------------------------------------------------------
// SelfTransFormer: Q/K/V conv1x1 projections + BatchNorm(training) + LeakyReLU,
// then per-head "KV attention": H = softmax_j(K^T V / sqrt(dh)), out = sum_j H Q.
// B=8, CIN=512, COUT=1024, P=2048, H=8, dh=128.
// Attention GEMMs run on tensor cores via tf32 mma.sync (m16n8k8).
// ---------------------------------------------------------------------------

#define BB   8
#define CIN  512
#define COUT 1024
#define PP   2048
#define NH   8
#define DH   128
#define EPSF 1e-5f

// scratch: Y[proj][b][cout][p], proj 0=Q,1=K,2=V  (192 MB)
static __device__ float g_Y[(size_t)3 * BB * COUT * PP];
// per (proj, channel): {scale, shift}
static __device__ float2 g_ss[3 * COUT];

// ---------------------------------------------------------------------------
// 1) Projection GEMM: Y[proj][b] = W_proj [1024x512] * X_b [512x2048]
// ---------------------------------------------------------------------------
__global__ void __launch_bounds__(256)
proj_gemm_kernel(const float* __restrict__ x,
                 const float* __restrict__ Wq,
                 const float* __restrict__ Wk,
                 const float* __restrict__ Wv)
{
    const int proj = blockIdx.z >> 3;
    const int b    = blockIdx.z & 7;
    const float* __restrict__ W = (proj == 0) ? Wq : ((proj == 1) ? Wk : Wv);
    const float* __restrict__ X = x + (size_t)b * CIN * PP;
    float* __restrict__ C = g_Y + ((size_t)(proj * BB + b) * COUT) * PP;

    const int row0 = blockIdx.y * 128;
    const int col0 = blockIdx.x * 128;

    __shared__ float As[2][8][128];
    __shared__ float Bs[2][8][128];

    const int t  = threadIdx.x;
    const int tx = t & 15;
    const int ty = t >> 4;
    const int tx8 = tx * 8, ty8 = ty * 8;

    const int ar = t >> 1;
    const int ak = (t & 1) * 4;
    const int bk = t >> 5;
    const int bc = (t & 31) * 4;

    float4 pa = *(const float4*)&W[(size_t)(row0 + ar) * CIN + ak];
    float4 pb = *(const float4*)&X[(size_t)bk * PP + col0 + bc];

    As[0][ak + 0][ar] = pa.x;
    As[0][ak + 1][ar] = pa.y;
    As[0][ak + 2][ar] = pa.z;
    As[0][ak + 3][ar] = pa.w;
    *(float4*)&Bs[0][bk][bc] = pb;
    __syncthreads();

    float acc[8][8];
#pragma unroll
    for (int r = 0; r < 8; r++)
#pragma unroll
        for (int q = 0; q < 8; q++) acc[r][q] = 0.f;

    const int KT = CIN / 8;
    for (int kt = 0; kt < KT; kt++) {
        const int cur = kt & 1;
        if (kt < KT - 1) {
            const int k0 = (kt + 1) * 8;
            pa = *(const float4*)&W[(size_t)(row0 + ar) * CIN + k0 + ak];
            pb = *(const float4*)&X[(size_t)(k0 + bk) * PP + col0 + bc];
        }
#pragma unroll
        for (int kk = 0; kk < 8; kk++) {
            float4 a0 = *(float4*)&As[cur][kk][ty8];
            float4 a1 = *(float4*)&As[cur][kk][ty8 + 4];
            float4 b0 = *(float4*)&Bs[cur][kk][tx8];
            float4 b1 = *(float4*)&Bs[cur][kk][tx8 + 4];
            float av[8] = {a0.x, a0.y, a0.z, a0.w, a1.x, a1.y, a1.z, a1.w};
            float bv[8] = {b0.x, b0.y, b0.z, b0.w, b1.x, b1.y, b1.z, b1.w};
#pragma unroll
            for (int r = 0; r < 8; r++)
#pragma unroll
                for (int q = 0; q < 8; q++)
                    acc[r][q] = fmaf(av[r], bv[q], acc[r][q]);
        }
        if (kt < KT - 1) {
            const int nxt = cur ^ 1;
            As[nxt][ak + 0][ar] = pa.x;
            As[nxt][ak + 1][ar] = pa.y;
            As[nxt][ak + 2][ar] = pa.z;
            As[nxt][ak + 3][ar] = pa.w;
            *(float4*)&Bs[nxt][bk][bc] = pb;
            __syncthreads();
        }
    }

#pragma unroll
    for (int r = 0; r < 8; r++) {
        float* crow = C + (size_t)(row0 + ty8 + r) * PP + col0 + tx8;
        *(float4*)(crow)     = make_float4(acc[r][0], acc[r][1], acc[r][2], acc[r][3]);
        *(float4*)(crow + 4) = make_float4(acc[r][4], acc[r][5], acc[r][6], acc[r][7]);
    }
}

// ---------------------------------------------------------------------------
// 2) BN stats per (proj, channel)
// ---------------------------------------------------------------------------
__global__ void __launch_bounds__(256)
stats_kernel(const float* __restrict__ gq, const float* __restrict__ bq,
             const float* __restrict__ gk, const float* __restrict__ bk,
             const float* __restrict__ gv, const float* __restrict__ bv)
{
    const int o    = blockIdx.x & (COUT - 1);
    const int proj = blockIdx.x >> 10;
    const int tid  = threadIdx.x;

    float s = 0.f, ss = 0.f;
    for (int b = 0; b < BB; b++) {
        const float4* row = (const float4*)(g_Y + (((size_t)(proj * BB + b) * COUT + o) * PP));
#pragma unroll
        for (int i = tid; i < PP / 4; i += 256) {
            float4 v = row[i];
            s  += v.x + v.y + v.z + v.w;
            ss += v.x * v.x + v.y * v.y + v.z * v.z + v.w * v.w;
        }
    }
#pragma unroll
    for (int off = 16; off; off >>= 1) {
        s  += __shfl_down_sync(0xffffffffu, s, off);
        ss += __shfl_down_sync(0xffffffffu, ss, off);
    }
    __shared__ float ws[8], wss[8];
    if ((tid & 31) == 0) { ws[tid >> 5] = s; wss[tid >> 5] = ss; }
    __syncthreads();
    if (tid == 0) {
        float S = 0.f, SS = 0.f;
#pragma unroll
        for (int i = 0; i < 8; i++) { S += ws[i]; SS += wss[i]; }
        const float invN = 1.0f / (float)(BB * PP);
        float mean = S * invN;
        float var  = SS * invN - mean * mean;
        float g    = (proj == 0) ? gq[o] : ((proj == 1) ? gk[o] : gv[o]);
        float be   = (proj == 0) ? bq[o] : ((proj == 1) ? bk[o] : bv[o]);
        float scale = g * rsqrtf(var + EPSF);
        g_ss[blockIdx.x] = make_float2(scale, be - mean * scale);
    }
}

// ---------------------------------------------------------------------------
// 3) Normalize + LeakyReLU(0.1) in place.
// ---------------------------------------------------------------------------
__global__ void __launch_bounds__(256)
norm_kernel()
{
    const size_t i4 = (size_t)blockIdx.x * 256 + threadIdx.x;
    const size_t e  = i4 * 4;
    const int o    = (int)((e >> 11) & (COUT - 1));
    const int proj = (int)(e >> 24);
    const float2 ss = g_ss[proj * COUT + o];
    float4* Y4 = (float4*)g_Y;
    float4 v = Y4[i4];
    float a = fmaf(v.x, ss.x, ss.y);
    float bq_ = fmaf(v.y, ss.x, ss.y);
    float c = fmaf(v.z, ss.x, ss.y);
    float d = fmaf(v.w, ss.x, ss.y);
    v.x = (a   >= 0.f) ? a   : 0.1f * a;
    v.y = (bq_ >= 0.f) ? bq_ : 0.1f * bq_;
    v.z = (c   >= 0.f) ? c   : 0.1f * c;
    v.w = (d   >= 0.f) ? d   : 0.1f * d;
    Y4[i4] = v;
}

// ---------------------------------------------------------------------------
// 4) Flash attention on tensor cores (tf32 mma.sync m16n8k8).
//    Per CTA: (b, h, 128-row i-tile). 8 warps x 16 rows each.
//    "queries" = K columns, "keys" = V columns, "values" = Q columns.
// ---------------------------------------------------------------------------
#define SK 132   // Kf stride (== 4 mod 32)
#define SV 72    // Vf stride (== 8 mod 32)
#define SQ 68    // Qf stride (== 4 mod 32)
#define SP 68    // Pw stride (== 4 mod 32)

#define ATTN_SMEM_FLOATS (128*SK + 128*SV + 128*SQ + 8*16*SP)
#define ATTN_SMEM_BYTES  (ATTN_SMEM_FLOATS * 4)

__device__ __forceinline__ float to_tf32(float x) {
    uint32_t u;
    asm("cvt.rna.tf32.f32 %0, %1;" : "=r"(u) : "f"(x));
    return __uint_as_float(u);
}

__device__ __forceinline__ void mma_tf32(float& d0, float& d1, float& d2, float& d3,
                                         uint32_t a0, uint32_t a1, uint32_t a2, uint32_t a3,
                                         uint32_t b0, uint32_t b1)
{
    asm volatile("mma.sync.aligned.m16n8k8.row.col.f32.tf32.tf32.f32 "
                 "{%0,%1,%2,%3}, {%4,%5,%6,%7}, {%8,%9}, {%0,%1,%2,%3};\n"
                 : "+f"(d0), "+f"(d1), "+f"(d2), "+f"(d3)
                 : "r"(a0), "r"(a1), "r"(a2), "r"(a3), "r"(b0), "r"(b1));
}

__global__ void __launch_bounds__(256)
attn_mma_kernel(float* __restrict__ out)
{
    extern __shared__ float sm[];
    float* Kf = sm;                        // [i=128][SK]  (K transposed, pre-scaled, tf32)
    float* Vf = Kf + 128 * SK;             // [c=128][SV]  (tf32)
    float* Qf = Vf + 128 * SV;             // [c=128][SQ]  (tf32)
    float* PwAll = Qf + 128 * SQ;          // 8 x [16][SP] (per-warp P, tf32)

    const int tid  = threadIdx.x;
    const int wid  = tid >> 5;
    const int lane = tid & 31;
    const int g    = lane >> 2;   // 0..7
    const int t    = lane & 3;    // 0..3
    float* Pw = PwAll + wid * (16 * SP);

    const int i0 = blockIdx.x * 128;
    const int h  = blockIdx.y;
    const int b  = blockIdx.z;
    const size_t headBase = ((size_t)b * COUT + h * DH) * PP;
    const float* __restrict__ Qn = g_Y + headBase;
    const float* __restrict__ Kn = g_Y + (size_t)BB * COUT * PP + headBase;
    const float* __restrict__ Vn = g_Y + (size_t)2 * BB * COUT * PP + headBase;

    const float rscale = 0.08838834764831845f;  // 1/sqrt(128)

    // Load K tile transposed: Kf[i][c] = K[c][i0+i] * rscale (tf32-rounded)
#pragma unroll
    for (int it = 0; it < 16; it++) {
        int lin = tid + it * 256;          // 0..4095
        int c  = lin >> 5;                 // 0..127
        int i4 = (lin & 31) << 2;          // 0..124
        float4 v = *(const float4*)&Kn[(size_t)c * PP + i0 + i4];
        Kf[(i4 + 0) * SK + c] = to_tf32(v.x * rscale);
        Kf[(i4 + 1) * SK + c] = to_tf32(v.y * rscale);
        Kf[(i4 + 2) * SK + c] = to_tf32(v.z * rscale);
        Kf[(i4 + 3) * SK + c] = to_tf32(v.w * rscale);
    }

    const int iw = wid * 16;
    float m0 = -1e30f, m1 = -1e30f, l0 = 0.f, l1 = 0.f;
    float o[16][4];
#pragma unroll
    for (int cf = 0; cf < 16; cf++)
#pragma unroll
        for (int u = 0; u < 4; u++) o[cf][u] = 0.f;

    for (int j0 = 0; j0 < PP; j0 += 64) {
        __syncthreads();   // previous iter's readers of Vf/Qf are done
        // Load V tile [c][j] and Q tile [c][j] (tf32-rounded)
#pragma unroll
        for (int it = 0; it < 8; it++) {
            int lin = tid + it * 256;      // 0..2047
            int c  = lin >> 4;             // 0..127
            int j4 = (lin & 15) << 2;      // 0..60
            float4 v = *(const float4*)&Vn[(size_t)c * PP + j0 + j4];
            *(float4*)&Vf[c * SV + j4] =
                make_float4(to_tf32(v.x), to_tf32(v.y), to_tf32(v.z), to_tf32(v.w));
            float4 q = *(const float4*)&Qn[(size_t)c * PP + j0 + j4];
            *(float4*)&Qf[c * SQ + j4] =
                make_float4(to_tf32(q.x), to_tf32(q.y), to_tf32(q.z), to_tf32(q.w));
        }
        __syncthreads();

        // ---- S gemm: S[16 i][64 j] per warp, K-dim c=128 ----
        float s[8][4];
#pragma unroll
        for (int nf = 0; nf < 8; nf++)
#pragma unroll
            for (int u = 0; u < 4; u++) s[nf][u] = 0.f;

#pragma unroll
        for (int kf = 0; kf < 16; kf++) {
            const int k0 = kf * 8;
            uint32_t a0 = __float_as_uint(Kf[(iw + g    ) * SK + k0 + t    ]);
            uint32_t a1 = __float_as_uint(Kf[(iw + g + 8) * SK + k0 + t    ]);
            uint32_t a2 = __float_as_uint(Kf[(iw + g    ) * SK + k0 + t + 4]);
            uint32_t a3 = __float_as_uint(Kf[(iw + g + 8) * SK + k0 + t + 4]);
#pragma unroll
            for (int nf = 0; nf < 8; nf++) {
                uint32_t b0 = __float_as_uint(Vf[(k0 + t    ) * SV + nf * 8 + g]);
                uint32_t b1 = __float_as_uint(Vf[(k0 + t + 4) * SV + nf * 8 + g]);
                mma_tf32(s[nf][0], s[nf][1], s[nf][2], s[nf][3], a0, a1, a2, a3, b0, b1);
            }
        }

        // ---- online softmax (warp-local; rows g and g+8) ----
        float mx0 = -1e30f, mx1 = -1e30f;
#pragma unroll
        for (int nf = 0; nf < 8; nf++) {
            mx0 = fmaxf(mx0, fmaxf(s[nf][0], s[nf][1]));
            mx1 = fmaxf(mx1, fmaxf(s[nf][2], s[nf][3]));
        }
        mx0 = fmaxf(mx0, __shfl_xor_sync(0xffffffffu, mx0, 1));
        mx0 = fmaxf(mx0, __shfl_xor_sync(0xffffffffu, mx0, 2));
        mx1 = fmaxf(mx1, __shfl_xor_sync(0xffffffffu, mx1, 1));
        mx1 = fmaxf(mx1, __shfl_xor_sync(0xffffffffu, mx1, 2));
        const float m0n = fmaxf(m0, mx0);
        const float m1n = fmaxf(m1, mx1);
        const float f0 = __expf(m0 - m0n);
        const float f1 = __expf(m1 - m1n);
        m0 = m0n; m1 = m1n;

        float sum0 = 0.f, sum1 = 0.f;
#pragma unroll
        for (int nf = 0; nf < 8; nf++) {
            float p0 = __expf(s[nf][0] - m0n);
            float p1 = __expf(s[nf][1] - m0n);
            float p2 = __expf(s[nf][2] - m1n);
            float p3 = __expf(s[nf][3] - m1n);
            sum0 += p0 + p1;
            sum1 += p2 + p3;
            *(float2*)&Pw[(g    ) * SP + nf * 8 + 2 * t] = make_float2(to_tf32(p0), to_tf32(p1));
            *(float2*)&Pw[(g + 8) * SP + nf * 8 + 2 * t] = make_float2(to_tf32(p2), to_tf32(p3));
        }
        sum0 += __shfl_xor_sync(0xffffffffu, sum0, 1);
        sum0 += __shfl_xor_sync(0xffffffffu, sum0, 2);
        sum1 += __shfl_xor_sync(0xffffffffu, sum1, 1);
        sum1 += __shfl_xor_sync(0xffffffffu, sum1, 2);
        l0 = l0 * f0 + sum0;
        l1 = l1 * f1 + sum1;

        // rescale O accumulators
#pragma unroll
        for (int cf = 0; cf < 16; cf++) {
            o[cf][0] *= f0; o[cf][1] *= f0;
            o[cf][2] *= f1; o[cf][3] *= f1;
        }
        __syncwarp();

        // ---- O gemm: O[16 i][128 c] per warp, K-dim j=64 ----
#pragma unroll
        for (int kf = 0; kf < 8; kf++) {
            const int k0 = kf * 8;
            uint32_t a0 = __float_as_uint(Pw[(g    ) * SP + k0 + t    ]);
            uint32_t a1 = __float_as_uint(Pw[(g + 8) * SP + k0 + t    ]);
            uint32_t a2 = __float_as_uint(Pw[(g    ) * SP + k0 + t + 4]);
            uint32_t a3 = __float_as_uint(Pw[(g + 8) * SP + k0 + t + 4]);
#pragma unroll
            for (int cf = 0; cf < 16; cf++) {
                uint32_t b0 = __float_as_uint(Qf[(cf * 8 + g) * SQ + k0 + t    ]);
                uint32_t b1 = __float_as_uint(Qf[(cf * 8 + g) * SQ + k0 + t + 4]);
                mma_tf32(o[cf][0], o[cf][1], o[cf][2], o[cf][3], a0, a1, a2, a3, b0, b1);
            }
        }
    }

    // ---- epilogue: out[c][i] = o / l ----
    const float inv0 = 1.0f / l0;
    const float inv1 = 1.0f / l1;
    const int ia = i0 + iw + g;
    const int ib = ia + 8;
#pragma unroll
    for (int cf = 0; cf < 16; cf++) {
        const int c = cf * 8 + 2 * t;
        out[headBase + (size_t)(c    ) * PP + ia] = o[cf][0] * inv0;
        out[headBase + (size_t)(c + 1) * PP + ia] = o[cf][1] * inv0;
        out[headBase + (size_t)(c    ) * PP + ib] = o[cf][2] * inv1;
        out[headBase + (size_t)(c + 1) * PP + ib] = o[cf][3] * inv1;
    }
}

// ---------------------------------------------------------------------------
extern "C" void kernel_launch(void* const* d_in, const int* in_sizes, int n_in,
                              void* d_out, int out_size)
{
    const float* x  = (const float*)d_in[0];
    const float* Wq = (const float*)d_in[1];
    const float* gq = (const float*)d_in[2];
    const float* bq = (const float*)d_in[3];
    const float* Wk = (const float*)d_in[4];
    const float* gk = (const float*)d_in[5];
    const float* bk = (const float*)d_in[6];
    const float* Wv = (const float*)d_in[7];
    const float* gv = (const float*)d_in[8];
    const float* bv = (const float*)d_in[9];
    float* out = (float*)d_out;

    (void)in_sizes; (void)n_in; (void)out_size;

    proj_gemm_kernel<<<dim3(PP / 128, COUT / 128, 24), 256>>>(x, Wq, Wk, Wv);
    stats_kernel<<<3 * COUT, 256>>>(gq, bq, gk, bk, gv, bv);
    norm_kernel<<<(3u * BB * COUT * PP / 4) / 256, 256>>>();

    cudaFuncSetAttribute(attn_mma_kernel,
                         cudaFuncAttributeMaxDynamicSharedMemorySize,
                         ATTN_SMEM_BYTES);
    attn_mma_kernel<<<dim3(PP / 128, NH, BB), 256, ATTN_SMEM_BYTES>>>(out);
}